// round 16
// baseline (speedup 1.0000x reference)
#include <cuda_runtime.h>
#include <cuda_bf16.h>
#include <cuda_fp16.h>
#include <cstdint>
#include <math.h>

#define KDIM 256
#define CDIM 128
#define P1_BLOCKS 148
#define MBLKS 782                      // ceil(100000/128); generic below guards via N

__device__ float    g_part[P1_BLOCKS * KDIM * CDIM];   // phase1 partials (fp32)
__device__ float    g_xsB[KDIM * CDIM];                // spectrum, fp16 B-frag layout
__device__ uint32_t g_Efrag[MBLKS * 8 * 2048];         // E in fp16 A-frag layout (51.25 MB)

// ---------------- helpers (sm_80-level PTX only) ----------------
__device__ __forceinline__ uint32_t packh2(float lo, float hi) {
    uint32_t r;
    asm("{\n\t.reg .f16 a, b;\n\tcvt.rn.f16.f32 a, %1;\n\tcvt.rn.f16.f32 b, %2;\n\t"
        "mov.b32 %0, {a, b};\n\t}" : "=r"(r) : "f"(lo), "f"(hi));
    return r;
}
__device__ __forceinline__ void mma16(float* d, const uint32_t* a, const uint32_t* b) {
    asm volatile(
        "mma.sync.aligned.m16n8k16.row.col.f32.f16.f16.f32 "
        "{%0,%1,%2,%3}, {%4,%5,%6,%7}, {%8,%9}, {%0,%1,%2,%3};"
        : "+f"(d[0]), "+f"(d[1]), "+f"(d[2]), "+f"(d[3])
        : "r"(a[0]), "r"(a[1]), "r"(a[2]), "r"(a[3]), "r"(b[0]), "r"(b[1]));
}
__device__ __forceinline__ uint32_t smem_u32(const void* p) {
    uint32_t a;
    asm("{ .reg .u64 t; cvta.to.shared.u64 t, %1; cvt.u32.u64 %0, t; }" : "=r"(a) : "l"(p));
    return a;
}
__device__ __forceinline__ void cpa16(uint32_t dst, const void* src) {
    asm volatile("cp.async.ca.shared.global [%0], [%1], 16;"
                 :: "r"(dst), "l"(src) : "memory");
}
#define CP_COMMIT() asm volatile("cp.async.commit_group;" ::: "memory")
#define CP_WAIT0()  asm volatile("cp.async.wait_group 0;" ::: "memory")

// f16 m16n8k16 frag maps:
//  A (mL 0..15, kk 0..15): lane=(mL&7)*4+((kk>>1)&3), reg=(mL>>3)+2*(kk>>3), half=kk&1
//  B (kk 0..15, nL 0..7):  lane=nL*4+((kk>>1)&3),     reg=kk>>3,             half=kk&1
//  D: c0,c1 -> row=l/4, col=2*(l%4)+{0,1}; c2,c3 -> row+8
// Efrag word (node,k even): (mb*8+kc)*2048 + (k16*8+mt)*128 + lane*4 + reg

// ---- Phase1 (R12 core, fp16): 32-node chunks, M-split CTAs ----
#define P1_K16S 1056
#define P1_FBUF 2112
#define P1_SMEM (4 * P1_FBUF * 4)      // 33792 B -> 2 CTAs/SM

// ---- Phase2 (fp16, frag-direct): 32-k chunks, 2-stage A frag + B ----
#define P2_BST  2048                   // u32 per B stage (x2, at 0 / 2048)
#define P2_AFS  2048                   // u32 per A frag stage (x2, at 4096 / 6144)
#define P2_SMEM (8192 * 4)             // 32768 B -> 2 CTAs/SM

// per-node row offset inside Efrag (in u32 words)
__device__ __forceinline__ uint32_t efrag_rowoff(int node) {
    return (uint32_t)((node >> 7) * 16384 + ((node >> 4) & 7) * 128
                    + (node & 7) * 16 + ((node >> 3) & 1));
}

// =====================================================================
// Phase 1 (fp16): partial[range][h*128+m][c] = E_half^T @ X,
// PLUS writes g_Efrag (fp16 A-fragment E) as byproduct.
// =====================================================================
__global__ void __launch_bounds__(256, 2)
phase1_kernel(const float* __restrict__ E, const float* __restrict__ X,
              int N, int chunk)
{
    extern __shared__ uint32_t sm[];
    uint32_t* Af = sm;
    uint32_t* Bf = sm + 2 * P1_FBUF;

    const int tid = threadIdx.x;
    const int warp = tid >> 5, lane = tid & 31;
    const int wm = warp >> 2;
    const int wn = warp & 3;
    const int h = blockIdx.y;

    uint32_t aoff[4], boff[4], kcst[4];
    int kp_[4], i2_[4];
    #pragma unroll
    for (int it = 0; it < 4; it++) {
        int slot = tid + it * 256;
        int kp = slot >> 6, i2 = slot & 63;
        kp_[it] = kp; i2_[it] = i2;
        int mL = (2 * i2) & 15, mt = i2 >> 3;
        aoff[it] = (uint32_t)((kp >> 3) * P1_K16S + mt * 132
                 + ((mL & 7) * 4 + (kp & 3)) * 4
                 + (mL >> 3) + 2 * ((kp >> 2) & 1));
        int ct = i2 >> 2, nL = (2 * i2) & 7;
        boff[it] = (uint32_t)((kp >> 3) * P1_K16S + ct * 66
                 + (nL * 4 + (kp & 3)) * 2 + ((kp >> 2) & 1));
        // Efrag k-constant for k = h*128 + 2*i2
        kcst[it] = (uint32_t)(h * 8192 + (i2 >> 4) * 2048 + ((i2 >> 3) & 1) * 1024
                 + (i2 & 3) * 4 + ((i2 >> 2) & 1) * 2);
    }
    const uint32_t alo = (uint32_t)(wm * 4 * 132 + lane * 4);
    const uint32_t blo = (uint32_t)(wn * 4 * 66 + lane * 2);

    float d[4][4][4];
    #pragma unroll
    for (int i = 0; i < 4; i++)
        #pragma unroll
        for (int j = 0; j < 4; j++)
            #pragma unroll
            for (int q = 0; q < 4; q++) d[i][j][q] = 0.f;

    const int nb = blockIdx.x * chunk;
    const int ne = min(N, nb + chunk);
    const int niter = (ne - nb + 31) >> 5;

    float2 curA[8], curB[8];
    const float2 z2 = make_float2(0.f, 0.f);

    auto loadc = [&](int s0) {
        #pragma unroll
        for (int it = 0; it < 4; it++) {
            int r0 = s0 + 2 * kp_[it];
            const float* pa = E + (size_t)r0 * KDIM + h * 128 + 2 * i2_[it];
            const float* pb = X + (size_t)r0 * CDIM + 2 * i2_[it];
            bool g0 = (r0 < ne), g1 = (r0 + 1 < ne);
            curA[2 * it]     = g0 ? *(const float2*)pa          : z2;
            curA[2 * it + 1] = g1 ? *(const float2*)(pa + KDIM) : z2;
            curB[2 * it]     = g0 ? *(const float2*)pb          : z2;
            curB[2 * it + 1] = g1 ? *(const float2*)(pb + CDIM) : z2;
        }
    };

    loadc(nb);

    for (int itn = 0; itn < niter; itn++) {
        const int buf = itn & 1;
        const int s0 = nb + itn * 32;
        uint32_t* Ab = Af + buf * P1_FBUF;
        uint32_t* Bb = Bf + buf * P1_FBUF;

        #pragma unroll
        for (int it = 0; it < 4; it++) {
            float2 ar = curA[2 * it], ar1 = curA[2 * it + 1];
            Ab[aoff[it]]      = packh2(ar.x, ar1.x);
            Ab[aoff[it] + 16] = packh2(ar.y, ar1.y);
            float2 br = curB[2 * it], br1 = curB[2 * it + 1];
            Bb[boff[it]]     = packh2(br.x, br1.x);
            Bb[boff[it] + 8] = packh2(br.y, br1.y);
            // Efrag byproduct stores (within-row k pairs)
            int n0 = s0 + 2 * kp_[it];
            if (n0 < ne)
                g_Efrag[kcst[it] + efrag_rowoff(n0)]     = packh2(ar.x, ar.y);
            if (n0 + 1 < ne)
                g_Efrag[kcst[it] + efrag_rowoff(n0 + 1)] = packh2(ar1.x, ar1.y);
        }
        __syncthreads();

        if (itn + 1 < niter) loadc(s0 + 32);

        #pragma unroll
        for (int k16 = 0; k16 < 2; k16++) {
            uint32_t a[4][4], b[4][2];
            #pragma unroll
            for (int i = 0; i < 4; i++) {
                uint4 av = *(const uint4*)(Ab + k16 * P1_K16S + alo + i * 132u);
                a[i][0] = av.x; a[i][1] = av.y; a[i][2] = av.z; a[i][3] = av.w;
            }
            #pragma unroll
            for (int j = 0; j < 4; j++) {
                uint2 bv = *(const uint2*)(Bb + k16 * P1_K16S + blo + j * 66u);
                b[j][0] = bv.x; b[j][1] = bv.y;
            }
            #pragma unroll
            for (int i = 0; i < 4; i++)
                #pragma unroll
                for (int j = 0; j < 4; j++)
                    mma16(d[i][j], a[i], b[j]);
        }
    }

    float* base = g_part + (size_t)blockIdx.x * (KDIM * CDIM);
    const int rql = lane >> 2, cql = (lane & 3) * 2;
    #pragma unroll
    for (int i = 0; i < 4; i++) {
        int row = h * 128 + wm * 64 + i * 16 + rql;
        #pragma unroll
        for (int j = 0; j < 4; j++) {
            int col = wn * 32 + j * 8 + cql;
            *(float2*)(base + row * CDIM + col)       = make_float2(d[i][j][0], d[i][j][1]);
            *(float2*)(base + (row + 8) * CDIM + col) = make_float2(d[i][j][2], d[i][j][3]);
        }
    }
}

// =====================================================================
// Reduce v3 (R14 proven): warp-group split-K, coalesced, smem combine.
// =====================================================================
__global__ void reduce_kernel(const float* __restrict__ evals,
                              const float* __restrict__ dt)
{
    __shared__ float red[3][64];

    const int tid = threadIdx.x;
    const int sl = tid >> 6;
    const int i  = tid & 63;
    const int idx = blockIdx.x * 64 + i;

    const float* p = g_part + (size_t)(sl * 37) * (KDIM * CDIM) + idx;
    float s0 = 0.f, s1 = 0.f, s2 = 0.f, s3 = 0.f;
    #pragma unroll
    for (int b = 0; b < 36; b += 4) {
        s0 += p[(size_t)(b + 0) * (KDIM * CDIM)];
        s1 += p[(size_t)(b + 1) * (KDIM * CDIM)];
        s2 += p[(size_t)(b + 2) * (KDIM * CDIM)];
        s3 += p[(size_t)(b + 3) * (KDIM * CDIM)];
    }
    s0 += p[(size_t)36 * (KDIM * CDIM)];
    float s = (s0 + s1) + (s2 + s3);

    if (sl > 0) red[sl - 1][i] = s;
    __syncthreads();

    if (sl == 0) {
        float v = s + red[0][i] + red[1][i] + red[2][i];
        int k = idx >> 7, c = idx & 127;
        float tt = fmaxf(dt[0], 1e-8f);
        v *= expf(-evals[k] * tt);

        int kc = k >> 5, k16l = (k >> 4) & 1, kk = k & 15;
        int ct = c >> 3, cL = c & 7;
        uint32_t word = (uint32_t)(kc * 2048
                      + ((k16l * 16 + ct) * 32 + cL * 4 + ((kk >> 1) & 3)) * 2
                      + (kk >> 3));
        __half* H = (__half*)g_xsB;
        H[word * 2 + (kk & 1)] = __float2half(v);
    }
}

// =====================================================================
// Phase 2 (fp16, frag-direct): out = E @ xs. M-tile 128, 8 warps.
// A fragments cp.async'd straight from g_Efrag (no repack, one sync/chunk).
// 32 KB smem -> 2 CTAs/SM.
// =====================================================================
__global__ void __launch_bounds__(256, 2)
phase2_kernel(float* __restrict__ out, int N)
{
    extern __shared__ uint32_t sm[];
    const uint32_t sbase = smem_u32(sm);

    const int tid = threadIdx.x;
    const int warp = tid >> 5, lane = tid & 31;
    const int wm = warp >> 2;
    const int wn = warp & 3;
    const int mb = blockIdx.x;
    const int m0 = mb * 128;

    auto copy_chunk = [&](int kc) {
        const int st = kc & 1;
        #pragma unroll
        for (int t = 0; t < 2; t++) {            // B frag: 8 KB contiguous
            int idx = tid + t * 256;
            cpa16(sbase + (uint32_t)(st * P2_BST + idx * 4) * 4,
                  (const uint32_t*)g_xsB + kc * 2048 + idx * 4);
        }
        #pragma unroll
        for (int t = 0; t < 2; t++) {            // A frag: 8 KB contiguous
            int idx = tid + t * 256;
            cpa16(sbase + (uint32_t)(4096 + st * P2_AFS + idx * 4) * 4,
                  g_Efrag + (size_t)(mb * 8 + kc) * 2048 + idx * 4);
        }
    };

    copy_chunk(0);
    CP_COMMIT();

    const uint32_t alo = (uint32_t)(wm * 4 * 32 + lane) * 4;
    const uint32_t blo = (uint32_t)(wn * 4 * 32 + lane) * 2;

    float d[4][4][4];
    #pragma unroll
    for (int i = 0; i < 4; i++)
        #pragma unroll
        for (int j = 0; j < 4; j++)
            #pragma unroll
            for (int q = 0; q < 4; q++) d[i][j][q] = 0.f;

    for (int kc = 0; kc < 8; kc++) {
        CP_WAIT0();
        __syncthreads();                 // chunk kc landed; MMA(kc-1) done

        if (kc + 1 < 8) { copy_chunk(kc + 1); CP_COMMIT(); }

        const uint32_t* Afs = sm + 4096 + (kc & 1) * P2_AFS;
        const uint32_t* Bf  = sm + (kc & 1) * P2_BST;
        #pragma unroll
        for (int k16 = 0; k16 < 2; k16++) {
            uint32_t a[4][4], b[4][2];
            #pragma unroll
            for (int i = 0; i < 4; i++) {
                uint4 av = *(const uint4*)(Afs + k16 * 1024 + alo + i * 128u);
                a[i][0] = av.x; a[i][1] = av.y; a[i][2] = av.z; a[i][3] = av.w;
            }
            #pragma unroll
            for (int j = 0; j < 4; j++) {
                uint2 bv = *(const uint2*)(Bf + k16 * 1024 + blo + j * 64u);
                b[j][0] = bv.x; b[j][1] = bv.y;
            }
            #pragma unroll
            for (int i = 0; i < 4; i++)
                #pragma unroll
                for (int j = 0; j < 4; j++)
                    mma16(d[i][j], a[i], b[j]);
        }
    }

    const int rql = lane >> 2, cql = (lane & 3) * 2;
    #pragma unroll
    for (int i = 0; i < 4; i++) {
        int row = m0 + wm * 64 + i * 16 + rql;
        #pragma unroll
        for (int j = 0; j < 4; j++) {
            int col = wn * 32 + j * 8 + cql;
            if (row < N)
                *(float2*)(out + (size_t)row * CDIM + col) = make_float2(d[i][j][0], d[i][j][1]);
            if (row + 8 < N)
                *(float2*)(out + (size_t)(row + 8) * CDIM + col) = make_float2(d[i][j][2], d[i][j][3]);
        }
    }
}

// =====================================================================
extern "C" void kernel_launch(void* const* d_in, const int* in_sizes, int n_in,
                              void* d_out, int out_size)
{
    const float* evals = nullptr;
    const float* dt = nullptr;
    long big_a = -1, big_b = -1; int ia = -1, ib = -1;
    for (int i = 0; i < n_in; i++) {
        long sz = in_sizes[i];
        if (sz == 1)         dt = (const float*)d_in[i];
        else if (sz == KDIM) evals = (const float*)d_in[i];
        else {
            if (sz > big_a) { big_b = big_a; ib = ia; big_a = sz; ia = i; }
            else if (sz > big_b) { big_b = sz; ib = i; }
        }
    }
    const float* evecs = (const float*)d_in[ia];   // N*K (largest)
    const float* x     = (const float*)d_in[ib];   // N*C
    const int N = (int)(big_b / CDIM);

    static int cfg = 0;
    if (!cfg) {
        cudaFuncSetAttribute(phase1_kernel, cudaFuncAttributeMaxDynamicSharedMemorySize, P1_SMEM);
        cudaFuncSetAttribute(phase2_kernel, cudaFuncAttributeMaxDynamicSharedMemorySize, P2_SMEM);
        cfg = 1;
    }

    const int chunk = (N + P1_BLOCKS - 1) / P1_BLOCKS;
    phase1_kernel<<<dim3(P1_BLOCKS, 2), 256, P1_SMEM>>>(evecs, x, N, chunk);
    reduce_kernel<<<512, 256>>>(evals, dt);
    phase2_kernel<<<(N + 127) / 128, 256, P2_SMEM>>>((float*)d_out, N);
}

// round 17
// speedup vs baseline: 1.0900x; 1.0900x over previous
#include <cuda_runtime.h>
#include <cuda_bf16.h>
#include <cuda_fp16.h>
#include <cstdint>
#include <math.h>

#define KDIM 256
#define CDIM 128
#define P1_BLOCKS 148

__device__ float g_part[P1_BLOCKS * KDIM * CDIM];   // phase1 partials (fp32)
__device__ float g_xsB[KDIM * CDIM];                // spectrum, fp16 B-frag layout

// ---------------- helpers (sm_80-level PTX only) ----------------
__device__ __forceinline__ uint32_t packh2(float lo, float hi) {
    uint32_t r;
    asm("{\n\t.reg .f16 a, b;\n\tcvt.rn.f16.f32 a, %1;\n\tcvt.rn.f16.f32 b, %2;\n\t"
        "mov.b32 %0, {a, b};\n\t}" : "=r"(r) : "f"(lo), "f"(hi));
    return r;
}
__device__ __forceinline__ void mma16(float* d, const uint32_t* a, const uint32_t* b) {
    asm volatile(
        "mma.sync.aligned.m16n8k16.row.col.f32.f16.f16.f32 "
        "{%0,%1,%2,%3}, {%4,%5,%6,%7}, {%8,%9}, {%0,%1,%2,%3};"
        : "+f"(d[0]), "+f"(d[1]), "+f"(d[2]), "+f"(d[3])
        : "r"(a[0]), "r"(a[1]), "r"(a[2]), "r"(a[3]), "r"(b[0]), "r"(b[1]));
}
__device__ __forceinline__ uint32_t smem_u32(const void* p) {
    uint32_t a;
    asm("{ .reg .u64 t; cvta.to.shared.u64 t, %1; cvt.u32.u64 %0, t; }" : "=r"(a) : "l"(p));
    return a;
}
__device__ __forceinline__ void cpa16(uint32_t dst, const void* src) {
    asm volatile("cp.async.ca.shared.global [%0], [%1], 16;"
                 :: "r"(dst), "l"(src) : "memory");
}
__device__ __forceinline__ void cpa16_cg(uint32_t dst, const void* src) {
    asm volatile("cp.async.cg.shared.global [%0], [%1], 16;"
                 :: "r"(dst), "l"(src) : "memory");
}
__device__ __forceinline__ float2 ldcs2(const float* p) {
    float2 v;
    asm("ld.global.cs.v2.f32 {%0, %1}, [%2];" : "=f"(v.x), "=f"(v.y) : "l"(p));
    return v;
}
__device__ __forceinline__ void stcs2(float* p, float2 v) {
    asm volatile("st.global.cs.v2.f32 [%0], {%1, %2};" :: "l"(p), "f"(v.x), "f"(v.y) : "memory");
}
__device__ __forceinline__ float ldcs1(const float* p) {
    float v; asm("ld.global.cs.f32 %0, [%1];" : "=f"(v) : "l"(p));
    return v;
}
#define CP_COMMIT() asm volatile("cp.async.commit_group;" ::: "memory")
#define CP_WAIT0()  asm volatile("cp.async.wait_group 0;" ::: "memory")

// f16 m16n8k16 frag maps:
//  A (mL 0..15, kk 0..15): lane=(mL&7)*4+((kk>>1)&3), reg=(mL>>3)+2*(kk>>3), half=kk&1
//  B (kk 0..15, nL 0..7):  lane=nL*4+((kk>>1)&3),     reg=kk>>3,             half=kk&1
//  D: c0,c1 -> row=l/4, col=2*(l%4)+{0,1}; c2,c3 -> row+8

// ---- Phase1 (R12 proven, fp16): 32-node chunks, M-split CTAs ----
#define P1_K16S 1056
#define P1_FBUF 2112
#define P1_SMEM (4 * P1_FBUF * 4)      // 33792 B -> 2 CTAs/SM

// ---- Phase2 (R12/R14 proven, fp16): 32-k chunks, 2-stage B + 2-stage raw A ----
#define P2_BST   2048
#define P2_ARAW  4096
#define P2_ARS   36
#define P2_ARAWU 4608
#define P2_AFRG  (P2_ARAW + 2 * P2_ARAWU)   // 13312
#define P2_TOT   (P2_AFRG + 2048)           // 15360 u32
#define P2_SMEM  (P2_TOT * 4)               // 61440 B -> 2 CTAs/SM

// =====================================================================
// Phase 1 (fp16): partial[range][h*128+m][c] = E_half^T @ X.
// E loads streamed (.cs, read-once); X default (.ca, L2-shared by pair);
// partials stores streamed (.cs).
// =====================================================================
__global__ void __launch_bounds__(256, 2)
phase1_kernel(const float* __restrict__ E, const float* __restrict__ X,
              int N, int chunk)
{
    extern __shared__ uint32_t sm[];
    uint32_t* Af = sm;
    uint32_t* Bf = sm + 2 * P1_FBUF;

    const int tid = threadIdx.x;
    const int warp = tid >> 5, lane = tid & 31;
    const int wm = warp >> 2;
    const int wn = warp & 3;
    const int h = blockIdx.y;

    uint32_t aoff[4], boff[4];
    int kp_[4], i2_[4];
    #pragma unroll
    for (int it = 0; it < 4; it++) {
        int slot = tid + it * 256;
        int kp = slot >> 6, i2 = slot & 63;
        kp_[it] = kp; i2_[it] = i2;
        int mL = (2 * i2) & 15, mt = i2 >> 3;
        aoff[it] = (uint32_t)((kp >> 3) * P1_K16S + mt * 132
                 + ((mL & 7) * 4 + (kp & 3)) * 4
                 + (mL >> 3) + 2 * ((kp >> 2) & 1));
        int ct = i2 >> 2, nL = (2 * i2) & 7;
        boff[it] = (uint32_t)((kp >> 3) * P1_K16S + ct * 66
                 + (nL * 4 + (kp & 3)) * 2 + ((kp >> 2) & 1));
    }
    const uint32_t alo = (uint32_t)(wm * 4 * 132 + lane * 4);
    const uint32_t blo = (uint32_t)(wn * 4 * 66 + lane * 2);

    float d[4][4][4];
    #pragma unroll
    for (int i = 0; i < 4; i++)
        #pragma unroll
        for (int j = 0; j < 4; j++)
            #pragma unroll
            for (int q = 0; q < 4; q++) d[i][j][q] = 0.f;

    const int nb = blockIdx.x * chunk;
    const int ne = min(N, nb + chunk);
    const int niter = (ne - nb + 31) >> 5;

    float2 curA[8], curB[8];
    const float2 z2 = make_float2(0.f, 0.f);

    auto loadc = [&](int s0) {
        #pragma unroll
        for (int it = 0; it < 4; it++) {
            int r0 = s0 + 2 * kp_[it];
            const float* pa = E + (size_t)r0 * KDIM + h * 128 + 2 * i2_[it];
            const float* pb = X + (size_t)r0 * CDIM + 2 * i2_[it];
            bool g0 = (r0 < ne), g1 = (r0 + 1 < ne);
            curA[2 * it]     = g0 ? ldcs2(pa)          : z2;
            curA[2 * it + 1] = g1 ? ldcs2(pa + KDIM)   : z2;
            curB[2 * it]     = g0 ? *(const float2*)pb          : z2;
            curB[2 * it + 1] = g1 ? *(const float2*)(pb + CDIM) : z2;
        }
    };

    loadc(nb);

    for (int itn = 0; itn < niter; itn++) {
        const int buf = itn & 1;
        uint32_t* Ab = Af + buf * P1_FBUF;
        uint32_t* Bb = Bf + buf * P1_FBUF;

        #pragma unroll
        for (int it = 0; it < 4; it++) {
            float2 ar = curA[2 * it], ar1 = curA[2 * it + 1];
            Ab[aoff[it]]      = packh2(ar.x, ar1.x);
            Ab[aoff[it] + 16] = packh2(ar.y, ar1.y);
            float2 br = curB[2 * it], br1 = curB[2 * it + 1];
            Bb[boff[it]]     = packh2(br.x, br1.x);
            Bb[boff[it] + 8] = packh2(br.y, br1.y);
        }
        __syncthreads();

        if (itn + 1 < niter) loadc(nb + (itn + 1) * 32);

        #pragma unroll
        for (int k16 = 0; k16 < 2; k16++) {
            uint32_t a[4][4], b[4][2];
            #pragma unroll
            for (int i = 0; i < 4; i++) {
                uint4 av = *(const uint4*)(Ab + k16 * P1_K16S + alo + i * 132u);
                a[i][0] = av.x; a[i][1] = av.y; a[i][2] = av.z; a[i][3] = av.w;
            }
            #pragma unroll
            for (int j = 0; j < 4; j++) {
                uint2 bv = *(const uint2*)(Bb + k16 * P1_K16S + blo + j * 66u);
                b[j][0] = bv.x; b[j][1] = bv.y;
            }
            #pragma unroll
            for (int i = 0; i < 4; i++)
                #pragma unroll
                for (int j = 0; j < 4; j++)
                    mma16(d[i][j], a[i], b[j]);
        }
    }

    float* base = g_part + (size_t)blockIdx.x * (KDIM * CDIM);
    const int rql = lane >> 2, cql = (lane & 3) * 2;
    #pragma unroll
    for (int i = 0; i < 4; i++) {
        int row = h * 128 + wm * 64 + i * 16 + rql;
        #pragma unroll
        for (int j = 0; j < 4; j++) {
            int col = wn * 32 + j * 8 + cql;
            stcs2(base + row * CDIM + col,       make_float2(d[i][j][0], d[i][j][1]));
            stcs2(base + (row + 8) * CDIM + col, make_float2(d[i][j][2], d[i][j][3]));
        }
    }
}

// =====================================================================
// Reduce v3 (R14 proven) + .cs loads: warp-group split-K, coalesced.
// =====================================================================
__global__ void reduce_kernel(const float* __restrict__ evals,
                              const float* __restrict__ dt)
{
    __shared__ float red[3][64];

    const int tid = threadIdx.x;
    const int sl = tid >> 6;
    const int i  = tid & 63;
    const int idx = blockIdx.x * 64 + i;

    const float* p = g_part + (size_t)(sl * 37) * (KDIM * CDIM) + idx;
    float s0 = 0.f, s1 = 0.f, s2 = 0.f, s3 = 0.f;
    #pragma unroll
    for (int b = 0; b < 36; b += 4) {
        s0 += ldcs1(p + (size_t)(b + 0) * (KDIM * CDIM));
        s1 += ldcs1(p + (size_t)(b + 1) * (KDIM * CDIM));
        s2 += ldcs1(p + (size_t)(b + 2) * (KDIM * CDIM));
        s3 += ldcs1(p + (size_t)(b + 3) * (KDIM * CDIM));
    }
    s0 += ldcs1(p + (size_t)36 * (KDIM * CDIM));
    float s = (s0 + s1) + (s2 + s3);

    if (sl > 0) red[sl - 1][i] = s;
    __syncthreads();

    if (sl == 0) {
        float v = s + red[0][i] + red[1][i] + red[2][i];
        int k = idx >> 7, c = idx & 127;
        float tt = fmaxf(dt[0], 1e-8f);
        v *= expf(-evals[k] * tt);

        int kc = k >> 5, k16l = (k >> 4) & 1, kk = k & 15;
        int ct = c >> 3, cL = c & 7;
        uint32_t word = (uint32_t)(kc * 2048
                      + ((k16l * 16 + ct) * 32 + cL * 4 + ((kk >> 1) & 3)) * 2
                      + (kk >> 3));
        __half* H = (__half*)g_xsB;
        H[word * 2 + (kk & 1)] = __float2half(v);
    }
}

// =====================================================================
// Phase 2 (fp16, R14 proven) + cache hints: A raw via cp.async.cg
// (L2-only), B via .ca (L2-hot, shared by all CTAs), out via .cs.
// =====================================================================
__global__ void __launch_bounds__(256, 2)
phase2_kernel(const float* __restrict__ E, float* __restrict__ out, int N)
{
    extern __shared__ uint32_t sm[];
    const uint32_t sbase = smem_u32(sm);

    const int tid = threadIdx.x;
    const int warp = tid >> 5, lane = tid & 31;
    const int wm = warp >> 2;
    const int wn = warp & 3;
    const int m0 = blockIdx.x * 128;

    auto copy_chunk = [&](int kc) {
        const int st = kc & 1;
        #pragma unroll
        for (int t = 0; t < 2; t++) {
            int idx = tid + t * 256;
            cpa16(sbase + (uint32_t)(st * P2_BST + idx * 4) * 4,
                  (const uint32_t*)g_xsB + kc * P2_BST + idx * 4);
        }
        #pragma unroll
        for (int t = 0; t < 4; t++) {
            int idx = tid + t * 256;
            int r = idx >> 3, j = idx & 7;
            int row = m0 + r; if (row >= N) row = N - 1;
            cpa16_cg(sbase + (uint32_t)(P2_ARAW + st * P2_ARAWU + r * P2_ARS + j * 4) * 4,
                     E + (size_t)row * KDIM + kc * 32 + j * 4);
        }
    };

    copy_chunk(0);
    CP_COMMIT();

    uint32_t fbase[2];
    int rk16_[2], rmt_[2], rl_[2];
    #pragma unroll
    for (int s = 0; s < 2; s++) {
        int sid = tid + s * 256;
        int k16 = sid >> 8, mt = (sid >> 5) & 7, l = sid & 31;
        rk16_[s] = k16; rmt_[s] = mt; rl_[s] = l;
        fbase[s] = (uint32_t)(((k16 * 8 + mt) * 32 + l) * 4);
    }
    const uint32_t alo = (uint32_t)(wm * 4 * 32 + lane) * 4;
    const uint32_t blo = (uint32_t)(wn * 4 * 32 + lane) * 2;

    float d[4][4][4];
    #pragma unroll
    for (int i = 0; i < 4; i++)
        #pragma unroll
        for (int j = 0; j < 4; j++)
            #pragma unroll
            for (int q = 0; q < 4; q++) d[i][j][q] = 0.f;

    uint32_t* Afrg = sm + P2_AFRG;

    for (int kc = 0; kc < 8; kc++) {
        CP_WAIT0();
        __syncthreads();

        if (kc + 1 < 8) { copy_chunk(kc + 1); CP_COMMIT(); }

        const float* Araw = (const float*)(sm + P2_ARAW + (kc & 1) * P2_ARAWU);
        #pragma unroll
        for (int s = 0; s < 2; s++) {
            const int k16 = rk16_[s], mt = rmt_[s], l = rl_[s];
            uint32_t w[4];
            #pragma unroll
            for (int q = 0; q < 4; q++) {
                int row = mt * 16 + (l >> 2) + 8 * (q & 1);
                int col = k16 * 16 + 2 * (l & 3) + 8 * (q >> 1);
                float2 v = *(const float2*)(Araw + row * P2_ARS + col);
                w[q] = packh2(v.x, v.y);
            }
            *(uint4*)(Afrg + fbase[s]) = make_uint4(w[0], w[1], w[2], w[3]);
        }
        __syncthreads();

        const uint32_t* Bf = sm + (kc & 1) * P2_BST;
        #pragma unroll
        for (int k16 = 0; k16 < 2; k16++) {
            uint32_t a[4][4], b[4][2];
            #pragma unroll
            for (int i = 0; i < 4; i++) {
                uint4 av = *(const uint4*)(Afrg + k16 * 1024 + alo + i * 128u);
                a[i][0] = av.x; a[i][1] = av.y; a[i][2] = av.z; a[i][3] = av.w;
            }
            #pragma unroll
            for (int j = 0; j < 4; j++) {
                uint2 bv = *(const uint2*)(Bf + k16 * 1024 + blo + j * 64u);
                b[j][0] = bv.x; b[j][1] = bv.y;
            }
            #pragma unroll
            for (int i = 0; i < 4; i++)
                #pragma unroll
                for (int j = 0; j < 4; j++)
                    mma16(d[i][j], a[i], b[j]);
        }
    }

    const int rql = lane >> 2, cql = (lane & 3) * 2;
    #pragma unroll
    for (int i = 0; i < 4; i++) {
        int row = m0 + wm * 64 + i * 16 + rql;
        #pragma unroll
        for (int j = 0; j < 4; j++) {
            int col = wn * 32 + j * 8 + cql;
            if (row < N)
                stcs2(out + (size_t)row * CDIM + col, make_float2(d[i][j][0], d[i][j][1]));
            if (row + 8 < N)
                stcs2(out + (size_t)(row + 8) * CDIM + col, make_float2(d[i][j][2], d[i][j][3]));
        }
    }
}

// =====================================================================
extern "C" void kernel_launch(void* const* d_in, const int* in_sizes, int n_in,
                              void* d_out, int out_size)
{
    const float* evals = nullptr;
    const float* dt = nullptr;
    long big_a = -1, big_b = -1; int ia = -1, ib = -1;
    for (int i = 0; i < n_in; i++) {
        long sz = in_sizes[i];
        if (sz == 1)         dt = (const float*)d_in[i];
        else if (sz == KDIM) evals = (const float*)d_in[i];
        else {
            if (sz > big_a) { big_b = big_a; ib = ia; big_a = sz; ia = i; }
            else if (sz > big_b) { big_b = sz; ib = i; }
        }
    }
    const float* evecs = (const float*)d_in[ia];   // N*K (largest)
    const float* x     = (const float*)d_in[ib];   // N*C
    const int N = (int)(big_b / CDIM);

    static int cfg = 0;
    if (!cfg) {
        cudaFuncSetAttribute(phase1_kernel, cudaFuncAttributeMaxDynamicSharedMemorySize, P1_SMEM);
        cudaFuncSetAttribute(phase2_kernel, cudaFuncAttributeMaxDynamicSharedMemorySize, P2_SMEM);
        cfg = 1;
    }

    const int chunk = (N + P1_BLOCKS - 1) / P1_BLOCKS;
    phase1_kernel<<<dim3(P1_BLOCKS, 2), 256, P1_SMEM>>>(evecs, x, N, chunk);
    reduce_kernel<<<512, 256>>>(evals, dt);
    phase2_kernel<<<(N + 127) / 128, 256, P2_SMEM>>>(evecs, (float*)d_out, N);
}